// round 5
// baseline (speedup 1.0000x reference)
#include <cuda_runtime.h>
#include <cuda_fp16.h>

// SinkhornDistance: B=64, N=M=1024, eps=0.1, 50 iterations.
// Scaling domain: K = exp(-C/eps); a = (mu+1e-8)/(K b); b = (nu+1e-8)/(K^T a)
// pi = exp(-C/eps) * a_i * b_j ; cost_b = sum pi*C.
//
// R5: single persistent kernel. 6 teams x 64 blocks (all co-resident at
// 3 blocks/SM). Team t processes batches t, t+6, ... sequentially; its 64
// blocks sync per iteration via a monotonic atomic barrier. Working set
// ~12MB -> fully L2 resident. K16 precompute folded into iter 0 (each block
// writes exactly the tile it re-reads). Epilogue folded in per batch.
// Folded multi-row warp reduce (31 shfl instead of 80).

#define BATCH 64
#define NN 1024
#define INV_EPS 10.0f
#define LOGEPS 1e-8f
#define MAX_ITER 50
#define EXP10 22026.4657948f  // exp(1/eps) -> b for v0 = 1

#define TEAMS 6
#define RPB 16               // rows per block
#define BPB 64               // blocks per team (= NN/RPB)

// Scratch (static device globals; no runtime allocation)
__device__ __half g_K16[(size_t)BATCH * NN * NN];  // 128 MB
__device__ float g_T[3][BATCH * NN];               // rotation buffers
__device__ unsigned g_bar[TEAMS];                  // team barrier counters

__device__ __forceinline__ unsigned ld_acquire(const unsigned* p) {
    unsigned v;
    asm volatile("ld.acquire.gpu.b32 %0, [%1];" : "=r"(v) : "l"(p) : "memory");
    return v;
}

// ---------------------------------------------------------------------------
// Zero T[0] (all batches), cost, and barrier counters. 64 blocks x 256.
__global__ void k_init(float* __restrict__ cost) {
    int idx = blockIdx.x * 256 + threadIdx.x;  // 16384 float4 = 64K floats
    ((float4*)g_T[0])[idx] = make_float4(0.f, 0.f, 0.f, 0.f);
    if (blockIdx.x == 0) {
        if (threadIdx.x < BATCH) cost[threadIdx.x] = 0.0f;
        if (threadIdx.x < TEAMS) g_bar[threadIdx.x] = 0u;
    }
}

// ---------------------------------------------------------------------------
__global__ void __launch_bounds__(256, 3) sinkhorn_persistent(
    const float* __restrict__ mu, const float* __restrict__ nu,
    const float* __restrict__ C, float* __restrict__ cost,
    float* __restrict__ pi)
{
    const int team = blockIdx.x / BPB;
    const int blk  = blockIdx.x % BPB;
    const int r0   = blk * RPB;
    const int tid  = threadIdx.x;
    const int lane = tid & 31, warp = tid >> 5;

    __shared__ float mush[RPB];
    __shared__ float ash[RPB];
    __shared__ float wsum[RPB][9];   // padded: conflict-free writes

    unsigned epoch = 0;

    for (int batch = team; batch < BATCH; batch += TEAMS) {
        // --- per-batch setup (no sync needed: mush read by same threads) ---
        if (tid < RPB)
            mush[tid] = mu[(size_t)batch * NN + r0 + tid] + LOGEPS;
        float4 nv = ((const float4*)(nu + (size_t)batch * NN))[tid];
        nv.x += LOGEPS; nv.y += LOGEPS; nv.z += LOGEPS; nv.w += LOGEPS;

        const uint2* __restrict__ Kb =
            (const uint2*)(g_K16 + (size_t)batch * NN * NN);
        uint2* __restrict__ Kbw = (uint2*)(g_K16 + (size_t)batch * NN * NN);

        for (int it = 0; it < MAX_ITER; it++) {
            // b at this thread's 4 columns
            float4 bv;
            if (it == 0) {
                bv = make_float4(EXP10, EXP10, EXP10, EXP10);
            } else {
                float4 t =
                    ((const float4*)&g_T[(it + 2) % 3][(size_t)batch * NN])[tid];
                bv.x = __fdividef(nv.x, t.x);
                bv.y = __fdividef(nv.y, t.y);
                bv.z = __fdividef(nv.z, t.z);
                bv.w = __fdividef(nv.w, t.w);
            }

            // Zero-ahead buffer (it+1)%3: last read at iteration it-1, which is
            // behind the team barrier -> race-free.
            if (blk == 0)
                ((float4*)&g_T[(it + 1) % 3][(size_t)batch * NN])[tid] =
                    make_float4(0.f, 0.f, 0.f, 0.f);

            // K tile (16 rows x 4 cols/thread) in registers.
            uint2 kv[RPB];
            if (it == 0) {
                // Fold precompute into iter 0: read C (DRAM), build fp16 K,
                // store the exact tile this block re-reads in iters 1..49.
#pragma unroll
                for (int r = 0; r < RPB; r++) {
                    float4 c = ((const float4*)(
                        C + ((size_t)batch * NN + r0 + r) * NN))[tid];
                    __half2 h0 = __floats2half2_rn(__expf(-c.x * INV_EPS),
                                                   __expf(-c.y * INV_EPS));
                    __half2 h1 = __floats2half2_rn(__expf(-c.z * INV_EPS),
                                                   __expf(-c.w * INV_EPS));
                    kv[r].x = *(const unsigned*)&h0;
                    kv[r].y = *(const unsigned*)&h1;
                    Kbw[(size_t)(r0 + r) * (NN / 4) + tid] = kv[r];
                }
            } else {
#pragma unroll
                for (int r = 0; r < RPB; r++)
                    kv[r] = Kb[(size_t)(r0 + r) * (NN / 4) + tid];
            }

            // Phase 1: per-row dot with b.
            float v[RPB];
#pragma unroll
            for (int r = 0; r < RPB; r++) {
                float2 f01 = __half22float2(*(__half2*)&kv[r].x);
                float2 f23 = __half22float2(*(__half2*)&kv[r].y);
                v[r] = f01.x * bv.x + f01.y * bv.y +
                       f23.x * bv.z + f23.y * bv.w;
            }
            // Folded multi-row warp reduce: 31 shfl for 16 rows.
#pragma unroll
            for (int r = 0; r < RPB; r++)
                v[r] += __shfl_xor_sync(0xffffffffu, v[r], 16);
            float u8[8];
#pragma unroll
            for (int j = 0; j < 8; j++) {
                u8[j] = (lane & 16) ? v[j + 8] : v[j];
                u8[j] += __shfl_xor_sync(0xffffffffu, u8[j], 8);
            }
            float u4[4];
#pragma unroll
            for (int j = 0; j < 4; j++) {
                u4[j] = (lane & 8) ? u8[j + 4] : u8[j];
                u4[j] += __shfl_xor_sync(0xffffffffu, u4[j], 4);
            }
            float u2[2];
#pragma unroll
            for (int j = 0; j < 2; j++) {
                u2[j] = (lane & 4) ? u4[j + 2] : u4[j];
                u2[j] += __shfl_xor_sync(0xffffffffu, u2[j], 2);
            }
            float q = (lane & 2) ? u2[1] : u2[0];
            q += __shfl_xor_sync(0xffffffffu, q, 1);
            int R = (lane >> 1) & 15;  // row owned by this lane (dup in lane^1)
            if (!(lane & 1)) wsum[R][warp] = q;
            __syncthreads();

            // Cross-warp combine + divide (tiny, smem-only).
            if (tid < RPB) {
                float s = 0.f;
#pragma unroll
                for (int w = 0; w < 8; w++) s += wsum[tid][w];
                ash[tid] = __fdividef(mush[tid], s);
            }
            __syncthreads();

            // Phase 2: column partials from the register tile.
            float4 acc = make_float4(0.f, 0.f, 0.f, 0.f);
#pragma unroll
            for (int r = 0; r < RPB; r++) {
                float a = ash[r];
                float2 f01 = __half22float2(*(__half2*)&kv[r].x);
                float2 f23 = __half22float2(*(__half2*)&kv[r].y);
                acc.x = fmaf(f01.x, a, acc.x);
                acc.y = fmaf(f01.y, a, acc.y);
                acc.z = fmaf(f23.x, a, acc.z);
                acc.w = fmaf(f23.y, a, acc.w);
            }
            float* T = &g_T[it % 3][(size_t)batch * NN] + tid * 4;
            atomicAdd(T + 0, acc.x);
            atomicAdd(T + 1, acc.y);
            atomicAdd(T + 2, acc.z);
            atomicAdd(T + 3, acc.w);

            // --- team barrier: all 64 blocks of this team finish iter `it` ---
            __threadfence();
            __syncthreads();
            epoch++;
            if (tid == 0) {
                atomicAdd(&g_bar[team], 1u);
                unsigned target = (unsigned)BPB * epoch;
                while (ld_acquire(&g_bar[team]) < target) __nanosleep(40);
            }
            __syncthreads();
        }

        // --- epilogue for this batch (ash holds final a for our rows) ---
        {
            float4 t =
                ((const float4*)&g_T[(MAX_ITER - 1) % 3][(size_t)batch * NN])[tid];
            float4 bv;
            bv.x = nv.x / t.x;
            bv.y = nv.y / t.y;
            bv.z = nv.z / t.z;
            bv.w = nv.w / t.w;

            float cacc = 0.0f;
#pragma unroll
            for (int r = 0; r < RPB; r++) {
                float a = ash[r];
                float4 cv = ((const float4*)(
                    C + ((size_t)batch * NN + r0 + r) * NN))[tid];
                float4 p;
                p.x = __expf(-cv.x * INV_EPS) * a * bv.x;
                p.y = __expf(-cv.y * INV_EPS) * a * bv.y;
                p.z = __expf(-cv.z * INV_EPS) * a * bv.z;
                p.w = __expf(-cv.w * INV_EPS) * a * bv.w;
                cacc += p.x * cv.x + p.y * cv.y + p.z * cv.z + p.w * cv.w;
                ((float4*)(pi + ((size_t)batch * NN + r0 + r) * NN))[tid] = p;
            }
#pragma unroll
            for (int o = 16; o; o >>= 1)
                cacc += __shfl_xor_sync(0xffffffffu, cacc, o);
            if (lane == 0) atomicAdd(&cost[batch], cacc);
        }
        // No inter-batch barrier needed: next batch touches disjoint buffers,
        // and ash reuse is protected by the first __syncthreads of iter 0.
    }
}

// ---------------------------------------------------------------------------
extern "C" void kernel_launch(void* const* d_in, const int* in_sizes, int n_in,
                              void* d_out, int out_size) {
    const float* mu = (const float*)d_in[0];
    const float* nu = (const float*)d_in[1];
    const float* C  = (const float*)d_in[2];
    float* cost = (float*)d_out;                 // outputs: (cost[64], pi[64M])
    float* pi   = (float*)d_out + BATCH;

    k_init<<<64, 256>>>(cost);
    sinkhorn_persistent<<<TEAMS * BPB, 256>>>(mu, nu, C, cost, pi);
}

// round 6
// speedup vs baseline: 1.9554x; 1.9554x over previous
#include <cuda_runtime.h>
#include <cuda_fp16.h>

// SinkhornDistance: B=64, N=M=1024, eps=0.1, 50 iterations.
// Scaling domain: K = exp(-C/eps); a = (mu+1e-8)/(K b); b = (nu+1e-8)/(K^T a)
// pi = exp(-C/eps) * a_i * b_j (fp32, on the fly) ; cost_b = sum pi*C.
//
// R6: launch-based (R3 structure) with the K tile staged in SHARED MEMORY
// instead of registers: regs ~80 -> ~45, occupancy ~34% -> ~65-75%, K still
// read from L2 exactly once per iteration (phase 1 uses the LDG registers
// directly in 4-row chunks while stashing to smem; phase 2 re-reads smem).

#define BATCH 64
#define NN 1024
#define INV_EPS 10.0f
#define LOGEPS 1e-8f
#define MAX_ITER 50
#define EXP10 22026.4657948f  // exp(1/eps) -> b for v0 = 1

#define GSZ 32               // batches per group (2 groups)
#define RPB 16               // rows per block
#define BPB (NN / RPB)       // 64 blocks per batch

// Scratch (static device globals; no runtime allocation)
__device__ __half g_K16[(size_t)BATCH * NN * NN];  // 128 MB
__device__ float g_a[BATCH * NN];
__device__ float g_T[3][BATCH * NN];               // rotation buffers

// ---------------------------------------------------------------------------
// K16 = fp16(exp(-C/eps)) for one group's slab. Thread handles 4 elements.
__global__ void __launch_bounds__(256) k_precompute16(const float* __restrict__ C,
                                                      int group_start) {
    size_t base = (size_t)group_start * NN * NN;
    size_t i = base + ((size_t)blockIdx.x * 256 + threadIdx.x) * 4;
    float4 c = *(const float4*)(C + i);
    __half2 h0 = __floats2half2_rn(__expf(-c.x * INV_EPS), __expf(-c.y * INV_EPS));
    __half2 h1 = __floats2half2_rn(__expf(-c.z * INV_EPS), __expf(-c.w * INV_EPS));
    uint2 pk;
    pk.x = *(const unsigned int*)&h0;
    pk.y = *(const unsigned int*)&h1;
    *(uint2*)(g_K16 + i) = pk;
}

// Zero cost[64] and T[0] for all batches. grid = 64 blocks x 256 threads.
__global__ void k_init(float* __restrict__ cost) {
    int idx = blockIdx.x * 256 + threadIdx.x;  // 16384 float4 = 64K floats
    ((float4*)g_T[0])[idx] = make_float4(0.f, 0.f, 0.f, 0.f);
    if (blockIdx.x == 0 && threadIdx.x < BATCH) cost[threadIdx.x] = 0.0f;
}

// ---------------------------------------------------------------------------
// Fused iteration on fp16 K. Block owns 16 rows of one batch; thread owns 4
// columns. K tile staged in smem (32KB); K read from L2 exactly once.
// Buffers: read T[(it+2)%3], write T[it%3], zero-ahead T[(it+1)%3].
__global__ void __launch_bounds__(256) fused_iter(
    const float* __restrict__ mu, const float* __restrict__ nu,
    int group_start, int iter)
{
    int batch = group_start + blockIdx.x / BPB;
    int r0 = (blockIdx.x % BPB) * RPB;
    int tid = threadIdx.x;
    int lane = tid & 31, warp = tid >> 5;

    __shared__ uint2 ktile[RPB][256];     // 32 KB fp16 tile stash
    __shared__ float mush[RPB];
    __shared__ float ash[RPB];
    __shared__ float wsum[RPB][9];        // padded

    // Prefetch mu for this block's rows (retires under phase 1).
    if (tid < RPB) mush[tid] = mu[(size_t)batch * NN + r0 + tid] + LOGEPS;

    // b at this thread's 4 columns
    float4 bv;
    if (iter == 0) {
        bv = make_float4(EXP10, EXP10, EXP10, EXP10);
    } else {
        float4 t = ((const float4*)&g_T[(iter + 2) % 3][(size_t)batch * NN])[tid];
        float4 n = ((const float4*)(nu + (size_t)batch * NN))[tid];
        bv.x = __fdividef(n.x + LOGEPS, t.x);
        bv.y = __fdividef(n.y + LOGEPS, t.y);
        bv.z = __fdividef(n.z + LOGEPS, t.z);
        bv.w = __fdividef(n.w + LOGEPS, t.w);
    }

    // Zero-ahead: buffer (iter+1)%3 is untouched by all other blocks this
    // launch (last read was the previous launch) -> race-free.
    if ((blockIdx.x % BPB) == 0) {
        ((float4*)&g_T[(iter + 1) % 3][(size_t)batch * NN])[tid] =
            make_float4(0.f, 0.f, 0.f, 0.f);
    }

    const uint2* __restrict__ Kb =
        (const uint2*)(g_K16 + (size_t)batch * NN * NN);

    // Phase 1: 4-row chunks — LDG, dot from registers, stash to smem.
    float part[RPB];
#pragma unroll
    for (int c = 0; c < RPB / 4; c++) {
        uint2 kv[4];
#pragma unroll
        for (int r = 0; r < 4; r++)
            kv[r] = Kb[(size_t)(r0 + c * 4 + r) * (NN / 4) + tid];
#pragma unroll
        for (int r = 0; r < 4; r++) {
            float2 f01 = __half22float2(*(__half2*)&kv[r].x);
            float2 f23 = __half22float2(*(__half2*)&kv[r].y);
            part[c * 4 + r] = f01.x * bv.x + f01.y * bv.y +
                              f23.x * bv.z + f23.y * bv.w;
            ktile[c * 4 + r][tid] = kv[r];
        }
    }

    // Folded multi-row warp reduce: 31 shfl for 16 rows.
#pragma unroll
    for (int r = 0; r < RPB; r++)
        part[r] += __shfl_xor_sync(0xffffffffu, part[r], 16);
    float u8[8];
#pragma unroll
    for (int j = 0; j < 8; j++) {
        u8[j] = (lane & 16) ? part[j + 8] : part[j];
        u8[j] += __shfl_xor_sync(0xffffffffu, u8[j], 8);
    }
    float u4[4];
#pragma unroll
    for (int j = 0; j < 4; j++) {
        u4[j] = (lane & 8) ? u8[j + 4] : u8[j];
        u4[j] += __shfl_xor_sync(0xffffffffu, u4[j], 4);
    }
    float u2[2];
#pragma unroll
    for (int j = 0; j < 2; j++) {
        u2[j] = (lane & 4) ? u4[j + 2] : u4[j];
        u2[j] += __shfl_xor_sync(0xffffffffu, u2[j], 2);
    }
    float q = (lane & 2) ? u2[1] : u2[0];
    q += __shfl_xor_sync(0xffffffffu, q, 1);
    int R = (lane >> 1) & 15;
    if (!(lane & 1)) wsum[R][warp] = q;
    __syncthreads();

    // Tiny critical section: smem-only + fast divide.
    if (tid < RPB) {
        float s = 0.f;
#pragma unroll
        for (int w = 0; w < 8; w++) s += wsum[tid][w];
        float a = __fdividef(mush[tid], s);
        ash[tid] = a;
        if (iter == MAX_ITER - 1) g_a[(size_t)batch * NN + r0 + tid] = a;
    }
    __syncthreads();

    // Phase 2: column partials re-reading the smem tile.
    float4 acc = make_float4(0.f, 0.f, 0.f, 0.f);
#pragma unroll
    for (int r = 0; r < RPB; r++) {
        float a = ash[r];
        uint2 kv = ktile[r][tid];
        float2 f01 = __half22float2(*(__half2*)&kv.x);
        float2 f23 = __half22float2(*(__half2*)&kv.y);
        acc.x = fmaf(f01.x, a, acc.x);
        acc.y = fmaf(f01.y, a, acc.y);
        acc.z = fmaf(f23.x, a, acc.z);
        acc.w = fmaf(f23.y, a, acc.w);
    }

    float* T = &g_T[iter % 3][(size_t)batch * NN] + tid * 4;
    atomicAdd(T + 0, acc.x);
    atomicAdd(T + 1, acc.y);
    atomicAdd(T + 2, acc.z);
    atomicAdd(T + 3, acc.w);
}

// ---------------------------------------------------------------------------
// Epilogue (per group): read C (fp32), K = exp(-C/eps) on the fly,
// pi = K*a_i*b_j (fp32), cost_b += sum pi*C. Final T buffer: (MAX_ITER-1)%3.
__global__ void __launch_bounds__(256) epilogue(
    const float* __restrict__ C, const float* __restrict__ nu,
    float* __restrict__ out_cost, float* __restrict__ out_pi, int group_start)
{
    __shared__ float bsh[NN];
    const int blocksPerBatch = NN / 8;
    int batch = group_start + blockIdx.x / blocksPerBatch;
    int rowBase = (blockIdx.x % blocksPerBatch) * 8;
    int tid = threadIdx.x;

    const float* __restrict__ T = &g_T[(MAX_ITER - 1) % 3][(size_t)batch * NN];
    for (int j = tid; j < NN; j += 256)
        bsh[j] = (nu[(size_t)batch * NN + j] + LOGEPS) / T[j];
    __syncthreads();

    int warp = tid >> 5, lane = tid & 31;
    int row = rowBase + warp;
    float a = g_a[(size_t)batch * NN + row];
    const float4* __restrict__ Crow =
        (const float4*)(C + ((size_t)batch * NN + row) * NN);
    float4* __restrict__ Prow =
        (float4*)(out_pi + ((size_t)batch * NN + row) * NN);
    const float4* __restrict__ bsh4 = (const float4*)bsh;

    float cacc = 0.0f;
#pragma unroll
    for (int k = 0; k < 8; k++) {
        int idx = k * 32 + lane;
        float4 cv = Crow[idx];
        float4 bv = bsh4[idx];
        float4 p;
        p.x = __expf(-cv.x * INV_EPS) * a * bv.x;
        p.y = __expf(-cv.y * INV_EPS) * a * bv.y;
        p.z = __expf(-cv.z * INV_EPS) * a * bv.z;
        p.w = __expf(-cv.w * INV_EPS) * a * bv.w;
        cacc += p.x * cv.x + p.y * cv.y + p.z * cv.z + p.w * cv.w;
        Prow[idx] = p;
    }
#pragma unroll
    for (int o = 16; o; o >>= 1) cacc += __shfl_xor_sync(0xffffffffu, cacc, o);
    if (lane == 0) atomicAdd(&out_cost[batch], cacc);
}

// ---------------------------------------------------------------------------
extern "C" void kernel_launch(void* const* d_in, const int* in_sizes, int n_in,
                              void* d_out, int out_size) {
    const float* mu = (const float*)d_in[0];
    const float* nu = (const float*)d_in[1];
    const float* C  = (const float*)d_in[2];
    float* cost = (float*)d_out;                 // outputs: (cost[64], pi[64M])
    float* pi   = (float*)d_out + BATCH;

    k_init<<<64, 256>>>(cost);

    const int precompBlocks = GSZ * NN * NN / (256 * 4);  // 32768
    for (int g = 0; g < BATCH / GSZ; g++) {
        int start = g * GSZ;
        k_precompute16<<<precompBlocks, 256>>>(C, start);
        for (int it = 0; it < MAX_ITER; it++) {
            fused_iter<<<GSZ * BPB, 256>>>(mu, nu, start, it);
        }
        epilogue<<<GSZ * (NN / 8), 256>>>(C, nu, cost, pi, start);
    }
}

// round 7
// speedup vs baseline: 2.8579x; 1.4616x over previous
#include <cuda_runtime.h>
#include <cuda_fp16.h>

// SinkhornDistance: B=64, N=M=1024, eps=0.1, 50 iterations.
// Scaling domain: K = exp(-C/eps); a = (mu+1e-8)/(K b); b = (nu+1e-8)/(K^T a)
// pi = exp(-C/eps) * a_i * b_j (fp32) ; cost_b = sum pi*C.
// b0 = 1 (valid: pi/cost exactly invariant to scaling b0; outputs only pi,cost).
//
// R7 (on R6's smem-staged tile):
//  - float4 atomicAdd for column sums (4x fewer LTS atomic ops -> decongests L2)
//  - half2 math for the phase-1 row dot (fewer instrs, no cvt in phase 1)

#define BATCH 64
#define NN 1024
#define INV_EPS 10.0f
#define LOGEPS 1e-8f
#define MAX_ITER 50

#define GSZ 32               // batches per group (2 groups)
#define RPB 16               // rows per block
#define BPB (NN / RPB)       // 64 blocks per batch

// Scratch (static device globals; no runtime allocation)
__device__ __half g_K16[(size_t)BATCH * NN * NN];  // 128 MB
__device__ float g_a[BATCH * NN];
__device__ float g_T[3][BATCH * NN];               // rotation buffers

// ---------------------------------------------------------------------------
// K16 = fp16(exp(-C/eps)) for one group's slab. Thread handles 4 elements.
__global__ void __launch_bounds__(256) k_precompute16(const float* __restrict__ C,
                                                      int group_start) {
    size_t base = (size_t)group_start * NN * NN;
    size_t i = base + ((size_t)blockIdx.x * 256 + threadIdx.x) * 4;
    float4 c = *(const float4*)(C + i);
    __half2 h0 = __floats2half2_rn(__expf(-c.x * INV_EPS), __expf(-c.y * INV_EPS));
    __half2 h1 = __floats2half2_rn(__expf(-c.z * INV_EPS), __expf(-c.w * INV_EPS));
    uint2 pk;
    pk.x = *(const unsigned int*)&h0;
    pk.y = *(const unsigned int*)&h1;
    *(uint2*)(g_K16 + i) = pk;
}

// Zero cost[64] and T[0] for all batches. grid = 64 blocks x 256 threads.
__global__ void k_init(float* __restrict__ cost) {
    int idx = blockIdx.x * 256 + threadIdx.x;  // 16384 float4 = 64K floats
    ((float4*)g_T[0])[idx] = make_float4(0.f, 0.f, 0.f, 0.f);
    if (blockIdx.x == 0 && threadIdx.x < BATCH) cost[threadIdx.x] = 0.0f;
}

// ---------------------------------------------------------------------------
// Fused iteration on fp16 K. Block owns 16 rows of one batch; thread owns 4
// columns. K tile staged in smem (32KB); K read from L2 exactly once.
// Buffers: read T[(it+2)%3], write T[it%3], zero-ahead T[(it+1)%3].
__global__ void __launch_bounds__(256) fused_iter(
    const float* __restrict__ mu, const float* __restrict__ nu,
    int group_start, int iter)
{
    int batch = group_start + blockIdx.x / BPB;
    int r0 = (blockIdx.x % BPB) * RPB;
    int tid = threadIdx.x;
    int lane = tid & 31, warp = tid >> 5;

    __shared__ uint2 ktile[RPB][256];     // 32 KB fp16 tile stash
    __shared__ float mush[RPB];
    __shared__ float ash[RPB];
    __shared__ float wsum[RPB][9];        // padded

    // Prefetch mu for this block's rows (retires under phase 1).
    if (tid < RPB) mush[tid] = mu[(size_t)batch * NN + r0 + tid] + LOGEPS;

    // b at this thread's 4 columns (half2 for the phase-1 dot).
    __half2 bh01, bh23;
    if (iter == 0) {
        bh01 = __floats2half2_rn(1.f, 1.f);
        bh23 = bh01;
    } else {
        float4 t = ((const float4*)&g_T[(iter + 2) % 3][(size_t)batch * NN])[tid];
        float4 n = ((const float4*)(nu + (size_t)batch * NN))[tid];
        bh01 = __floats2half2_rn(__fdividef(n.x + LOGEPS, t.x),
                                 __fdividef(n.y + LOGEPS, t.y));
        bh23 = __floats2half2_rn(__fdividef(n.z + LOGEPS, t.z),
                                 __fdividef(n.w + LOGEPS, t.w));
    }

    // Zero-ahead: buffer (iter+1)%3 is untouched by all other blocks this
    // launch (last read was the previous launch) -> race-free.
    if ((blockIdx.x % BPB) == 0) {
        ((float4*)&g_T[(iter + 1) % 3][(size_t)batch * NN])[tid] =
            make_float4(0.f, 0.f, 0.f, 0.f);
    }

    const uint2* __restrict__ Kb =
        (const uint2*)(g_K16 + (size_t)batch * NN * NN);

    // Phase 1: 4-row chunks — LDG, half2 dot from registers, stash to smem.
    float part[RPB];
#pragma unroll
    for (int c = 0; c < RPB / 4; c++) {
        uint2 kv[4];
#pragma unroll
        for (int r = 0; r < 4; r++)
            kv[r] = Kb[(size_t)(r0 + c * 4 + r) * (NN / 4) + tid];
#pragma unroll
        for (int r = 0; r < 4; r++) {
            __half2 k01 = *(__half2*)&kv[r].x;
            __half2 k23 = *(__half2*)&kv[r].y;
            __half2 p = __hfma2(k23, bh23, __hmul2(k01, bh01));
            float2 pf = __half22float2(p);
            part[c * 4 + r] = pf.x + pf.y;
            ktile[c * 4 + r][tid] = kv[r];
        }
    }

    // Folded multi-row warp reduce: 31 shfl for 16 rows.
#pragma unroll
    for (int r = 0; r < RPB; r++)
        part[r] += __shfl_xor_sync(0xffffffffu, part[r], 16);
    float u8[8];
#pragma unroll
    for (int j = 0; j < 8; j++) {
        u8[j] = (lane & 16) ? part[j + 8] : part[j];
        u8[j] += __shfl_xor_sync(0xffffffffu, u8[j], 8);
    }
    float u4[4];
#pragma unroll
    for (int j = 0; j < 4; j++) {
        u4[j] = (lane & 8) ? u8[j + 4] : u8[j];
        u4[j] += __shfl_xor_sync(0xffffffffu, u4[j], 4);
    }
    float u2[2];
#pragma unroll
    for (int j = 0; j < 2; j++) {
        u2[j] = (lane & 4) ? u4[j + 2] : u4[j];
        u2[j] += __shfl_xor_sync(0xffffffffu, u2[j], 2);
    }
    float q = (lane & 2) ? u2[1] : u2[0];
    q += __shfl_xor_sync(0xffffffffu, q, 1);
    int R = (lane >> 1) & 15;
    if (!(lane & 1)) wsum[R][warp] = q;
    __syncthreads();

    // Tiny critical section: smem-only + fast divide.
    if (tid < RPB) {
        float s = 0.f;
#pragma unroll
        for (int w = 0; w < 8; w++) s += wsum[tid][w];
        float a = __fdividef(mush[tid], s);
        ash[tid] = a;
        if (iter == MAX_ITER - 1) g_a[(size_t)batch * NN + r0 + tid] = a;
    }
    __syncthreads();

    // Phase 2: column partials re-reading the smem tile (fp32 accumulate).
    float4 acc = make_float4(0.f, 0.f, 0.f, 0.f);
#pragma unroll
    for (int r = 0; r < RPB; r++) {
        float a = ash[r];
        uint2 kv = ktile[r][tid];
        float2 f01 = __half22float2(*(__half2*)&kv.x);
        float2 f23 = __half22float2(*(__half2*)&kv.y);
        acc.x = fmaf(f01.x, a, acc.x);
        acc.y = fmaf(f01.y, a, acc.y);
        acc.z = fmaf(f23.x, a, acc.z);
        acc.w = fmaf(f23.y, a, acc.w);
    }

    // Single vector atomic per thread (sm_90+): 4x fewer LTS atomic ops.
    float4* T4 = (float4*)(&g_T[iter % 3][(size_t)batch * NN] + tid * 4);
    atomicAdd(T4, acc);
}

// ---------------------------------------------------------------------------
// Epilogue (per group): read C (fp32), K = exp(-C/eps) on the fly,
// pi = K*a_i*b_j (fp32), cost_b += sum pi*C. Final T buffer: (MAX_ITER-1)%3.
__global__ void __launch_bounds__(256) epilogue(
    const float* __restrict__ C, const float* __restrict__ nu,
    float* __restrict__ out_cost, float* __restrict__ out_pi, int group_start)
{
    __shared__ float bsh[NN];
    const int blocksPerBatch = NN / 8;
    int batch = group_start + blockIdx.x / blocksPerBatch;
    int rowBase = (blockIdx.x % blocksPerBatch) * 8;
    int tid = threadIdx.x;

    const float* __restrict__ T = &g_T[(MAX_ITER - 1) % 3][(size_t)batch * NN];
    for (int j = tid; j < NN; j += 256)
        bsh[j] = (nu[(size_t)batch * NN + j] + LOGEPS) / T[j];
    __syncthreads();

    int warp = tid >> 5, lane = tid & 31;
    int row = rowBase + warp;
    float a = g_a[(size_t)batch * NN + row];
    const float4* __restrict__ Crow =
        (const float4*)(C + ((size_t)batch * NN + row) * NN);
    float4* __restrict__ Prow =
        (float4*)(out_pi + ((size_t)batch * NN + row) * NN);
    const float4* __restrict__ bsh4 = (const float4*)bsh;

    float cacc = 0.0f;
#pragma unroll
    for (int k = 0; k < 8; k++) {
        int idx = k * 32 + lane;
        float4 cv = Crow[idx];
        float4 bv = bsh4[idx];
        float4 p;
        p.x = __expf(-cv.x * INV_EPS) * a * bv.x;
        p.y = __expf(-cv.y * INV_EPS) * a * bv.y;
        p.z = __expf(-cv.z * INV_EPS) * a * bv.z;
        p.w = __expf(-cv.w * INV_EPS) * a * bv.w;
        cacc += p.x * cv.x + p.y * cv.y + p.z * cv.z + p.w * cv.w;
        Prow[idx] = p;
    }
#pragma unroll
    for (int o = 16; o; o >>= 1) cacc += __shfl_xor_sync(0xffffffffu, cacc, o);
    if (lane == 0) atomicAdd(&out_cost[batch], cacc);
}

// ---------------------------------------------------------------------------
extern "C" void kernel_launch(void* const* d_in, const int* in_sizes, int n_in,
                              void* d_out, int out_size) {
    const float* mu = (const float*)d_in[0];
    const float* nu = (const float*)d_in[1];
    const float* C  = (const float*)d_in[2];
    float* cost = (float*)d_out;                 // outputs: (cost[64], pi[64M])
    float* pi   = (float*)d_out + BATCH;

    k_init<<<64, 256>>>(cost);

    const int precompBlocks = GSZ * NN * NN / (256 * 4);  // 32768
    for (int g = 0; g < BATCH / GSZ; g++) {
        int start = g * GSZ;
        k_precompute16<<<precompBlocks, 256>>>(C, start);
        for (int it = 0; it < MAX_ITER; it++) {
            fused_iter<<<GSZ * BPB, 256>>>(mu, nu, start, it);
        }
        epilogue<<<GSZ * (NN / 8), 256>>>(C, nu, cost, pi, start);
    }
}